// round 10
// baseline (speedup 1.0000x reference)
#include <cuda_runtime.h>
#include <cstdint>
#include <cstddef>

#define NB 64
#define NC 256
#define NL 4096
#define LT 4

// ---------------- scratch (device globals; no allocation allowed) ----------
__device__ float d_M [NC * NC];                 // Wq^T Wk / sqrt(C)
__device__ float d_W2[NC * NC];                 // Wout @ Wc
__device__ float d_g   [(size_t)NB * NC * NL];  // M @ x
__device__ float d_v   [(size_t)NB * NC * NL];  // Wv @ x
__device__ float d_virt[(size_t)NB * NC * NL];  // attention output
__device__ float d_mean[NB];
__device__ float d_rstd[NB];
// tf32-pre-rounded operands (fp32 bit patterns with rna-rounded mantissa)
__device__ float d_A0[512 * 256];               // rna([M ; Wv])
__device__ float d_A1[256 * 512];               // rna([Wout | W2])
__device__ float d_xtf[(size_t)NB * NC * NL];   // rna(x)
__device__ float d_vtf[(size_t)NB * NC * NL];   // rna(relu(gn(virt)))

// ---------------- helpers ---------------------------------------------------
__device__ __forceinline__ float f2tf(float v) {
    uint32_t u;
    asm("cvt.rna.tf32.f32 %0, %1;" : "=r"(u) : "f"(v));
    return __uint_as_float(u);
}
__device__ __forceinline__ void mma_tf32(float* c, const uint32_t* a,
                                         const uint32_t* b) {
    asm volatile(
        "mma.sync.aligned.m16n8k8.row.col.f32.tf32.tf32.f32 "
        "{%0,%1,%2,%3}, {%4,%5,%6,%7}, {%8,%9}, {%0,%1,%2,%3};"
        : "+f"(c[0]), "+f"(c[1]), "+f"(c[2]), "+f"(c[3])
        : "r"(a[0]), "r"(a[1]), "r"(a[2]), "r"(a[3]), "r"(b[0]), "r"(b[1]));
}
__device__ __forceinline__ uint32_t smem_u32(const void* p) {
    uint32_t a;
    asm("{ .reg .u64 t; cvta.to.shared.u64 t, %1; cvt.u32.u64 %0, t; }"
        : "=r"(a) : "l"(p));
    return a;
}
__device__ __forceinline__ void cp16(uint32_t dst, const float* src) {
    asm volatile("cp.async.ca.shared.global [%0], [%1], 16;"
                 :: "r"(dst), "l"(src));
}
__device__ __forceinline__ void cp_commit() {
    asm volatile("cp.async.commit_group;" ::: "memory");
}
__device__ __forceinline__ void cp_wait1() {
    asm volatile("cp.async.wait_group 1;" ::: "memory");
}
__device__ __forceinline__ void cp_wait0() {
    asm volatile("cp.async.wait_group 0;" ::: "memory");
}

// ---------------- K0: M = Wq^T Wk / 16 -------------------------------------
__global__ void k0_M(const float* __restrict__ Wq, const float* __restrict__ Wk) {
    __shared__ float sA[16][17], sB[16][17];
    int tx = threadIdx.x, ty = threadIdx.y;
    int c1 = blockIdx.y * 16 + ty;
    int c2 = blockIdx.x * 16 + tx;
    float acc = 0.f;
    for (int o0 = 0; o0 < NC; o0 += 16) {
        sA[ty][tx] = Wq[(o0 + ty) * NC + blockIdx.y * 16 + tx];
        sB[ty][tx] = Wk[(o0 + ty) * NC + blockIdx.x * 16 + tx];
        __syncthreads();
#pragma unroll
        for (int i = 0; i < 16; i++) acc += sA[i][ty] * sB[i][tx];
        __syncthreads();
    }
    d_M[c1 * NC + c2] = acc * 0.0625f;
}

// ---------------- K0b: W2 = Wout @ Wc --------------------------------------
__global__ void k0_W2(const float* __restrict__ Wout, const float* __restrict__ Wc) {
    __shared__ float sA[16][17], sB[16][17];
    int tx = threadIdx.x, ty = threadIdx.y;
    int o = blockIdx.y * 16 + ty;
    int c = blockIdx.x * 16 + tx;
    float acc = 0.f;
    for (int m0 = 0; m0 < NC; m0 += 16) {
        sA[ty][tx] = Wout[o * NC + m0 + tx];
        sB[ty][tx] = Wc[(m0 + ty) * NC + blockIdx.x * 16 + tx];
        __syncthreads();
#pragma unroll
        for (int i = 0; i < 16; i++) acc += sA[ty][i] * sB[i][tx];
        __syncthreads();
    }
    d_W2[o * NC + c] = acc;
}

// ---------------- prepass: round A matrices to tf32 -------------------------
__global__ void kprep_A(const float* __restrict__ Wv, const float* __restrict__ Wout) {
    int i = blockIdx.x * 256 + threadIdx.x;          // 0..131071
    float a = (i < 65536) ? d_M[i] : Wv[i - 65536];
    d_A0[i] = f2tf(a);
    int r = i >> 9, k = i & 511;
    float b2 = (k < 256) ? Wout[r * 256 + k] : d_W2[r * 256 + (k - 256)];
    d_A1[i] = f2tf(b2);
}

// ---------------- prepass: round x to tf32 ----------------------------------
__global__ void kcvt_x(const float* __restrict__ x) {
    size_t i = (size_t)blockIdx.x * 256 + threadIdx.x;   // float4 index
    float4 v = ((const float4*)x)[i];
    v.x = f2tf(v.x); v.y = f2tf(v.y); v.z = f2tf(v.z); v.w = f2tf(v.w);
    ((float4*)d_xtf)[i] = v;
}

// ------- prepass: gn affine + relu + tf32 round on virt ---------------------
__global__ void kcvt_v(const float* __restrict__ gamma, const float* __restrict__ beta) {
    size_t i = (size_t)blockIdx.x * 256 + threadIdx.x;   // float4 index
    int row = (int)(i >> 10);                            // b*256 + c  (NL/4=1024)
    int b = row >> 8, c = row & 255;
    float rs = d_rstd[b];
    float gsc = gamma[c] * rs;
    float bt  = beta[c] - d_mean[b] * gsc;
    float4 v = ((const float4*)d_virt)[i];
    v.x = f2tf(fmaxf(fmaf(v.x, gsc, bt), 0.f));
    v.y = f2tf(fmaxf(fmaf(v.y, gsc, bt), 0.f));
    v.z = f2tf(fmaxf(fmaf(v.z, gsc, bt), 0.f));
    v.w = f2tf(fmaxf(fmaf(v.w, gsc, bt), 0.f));
    ((float4*)d_vtf)[i] = v;
}

// ---------------- TF32 tensor-core GEMM (cp.async 2-stage pipeline) ---------
// mode 0: Y[512,L] = d_A0 @ d_xtf[b]^T        -> d_g / d_v   (K = 256)
// mode 1: out[256,L] = d_A1 @ [d_xtf ; d_vtf]^T              (K = 512)
// CTA tile 128(m) x 128(l), k-chunk 32, 8 warps (2m x 4n), warp tile 64x32.
// dyn smem: As[2][128][36] (floats 0..9215), Bs[2][32][136] (floats 9216..17919)
#define KG_SMEM ((2 * 128 * 36 + 2 * 32 * 136) * 4)

__device__ __forceinline__ void kg_issue(int mode, int ch, int tid, int b, int l0,
                                         const float* Abase, int Kst,
                                         uint32_t sbase) {
    int st = ch & 1;
    const float* Asrc = Abase + ch * 32;
#pragma unroll
    for (int j = 0; j < 4; j++) {
        int f = tid + 256 * j;
        int r = f >> 3, s = f & 7;
        uint32_t dst = sbase + (uint32_t)(st * 4608 + r * 36 + s * 4) * 4;
        cp16(dst, Asrc + (size_t)r * Kst + s * 4);
    }
    int kg0 = ch * 32;
    const float* Bsrc;
    if (!mode || kg0 < 256)
        Bsrc = d_xtf + ((size_t)b * NC + kg0) * NL + l0;
    else
        Bsrc = d_vtf + ((size_t)b * NC + (kg0 - 256)) * NL + l0;
#pragma unroll
    for (int j = 0; j < 4; j++) {
        int f = tid + 256 * j;
        int kr = f >> 5, s = f & 31;
        uint32_t dst = sbase + (uint32_t)(9216 + st * 4352 + kr * 136 + s * 4) * 4;
        cp16(dst, Bsrc + (size_t)kr * NL + s * 4);
    }
    cp_commit();
}

__global__ __launch_bounds__(256, 2) void k_gemm(int mode, float* __restrict__ out) {
    extern __shared__ float sm[];
    float (*As)[128][36] = (float (*)[128][36])sm;
    float (*Bs)[32][136] = (float (*)[32][136])(sm + 2 * 128 * 36);
    uint32_t sbase = smem_u32(sm);

    int tid = threadIdx.x;
    int b   = blockIdx.z;
    int l0  = blockIdx.y * 128;
    int m0  = blockIdx.x * 128;
    int nch = mode ? 16 : 8;
    int Kst = mode ? 512 : 256;
    const float* Abase = (mode ? d_A1 : d_A0) + (size_t)m0 * Kst;

    float* Ybase;
    int mbase;
    if (mode == 0) {
        if (m0 < 256) { Ybase = d_g; mbase = m0; }
        else          { Ybase = d_v; mbase = m0 - 256; }
    } else {
        Ybase = out; mbase = m0;
    }

    int lane = tid & 31, w = tid >> 5;
    int g = lane >> 2, tg = lane & 3;
    int wm = (w & 1) * 64, wn = (w >> 1) * 32;

    float acc[4][4][4];
#pragma unroll
    for (int mt = 0; mt < 4; mt++)
#pragma unroll
        for (int nt = 0; nt < 4; nt++)
#pragma unroll
            for (int i = 0; i < 4; i++) acc[mt][nt][i] = 0.f;

    kg_issue(mode, 0, tid, b, l0, Abase, Kst, sbase);

#pragma unroll 1
    for (int ch = 0; ch < nch; ch++) {
        if (ch + 1 < nch) {
            kg_issue(mode, ch + 1, tid, b, l0, Abase, Kst, sbase);
            cp_wait1();
        } else {
            cp_wait0();
        }
        __syncthreads();
        int st = ch & 1;
#pragma unroll
        for (int ks = 0; ks < 4; ks++) {
            int kb = ks * 8;
            uint32_t bf[4][2];
#pragma unroll
            for (int nt = 0; nt < 4; nt++) {
                bf[nt][0] = *(uint32_t*)&Bs[st][kb + tg][wn + nt * 8 + g];
                bf[nt][1] = *(uint32_t*)&Bs[st][kb + tg + 4][wn + nt * 8 + g];
            }
            uint32_t af[4][4];
#pragma unroll
            for (int mt = 0; mt < 4; mt++) {
                int rb = wm + mt * 16;
                af[mt][0] = *(uint32_t*)&As[st][rb + g][kb + tg];
                af[mt][1] = *(uint32_t*)&As[st][rb + g + 8][kb + tg];
                af[mt][2] = *(uint32_t*)&As[st][rb + g][kb + tg + 4];
                af[mt][3] = *(uint32_t*)&As[st][rb + g + 8][kb + tg + 4];
            }
#pragma unroll
            for (int mt = 0; mt < 4; mt++)
#pragma unroll
                for (int nt = 0; nt < 4; nt++)
                    mma_tf32(acc[mt][nt], af[mt], bf[nt]);
        }
        __syncthreads();
    }

    // ---- epilogue: fp32 stores ----
#pragma unroll
    for (int mt = 0; mt < 4; mt++) {
        int m = mbase + wm + mt * 16 + g;
        float* y0 = Ybase + ((size_t)b * NC + m) * NL + l0;
        float* y1 = Ybase + ((size_t)b * NC + m + 8) * NL + l0;
#pragma unroll
        for (int nt = 0; nt < 4; nt++) {
            int l = wn + nt * 8 + 2 * tg;
            y0[l]     = acc[mt][nt][0];
            y0[l + 1] = acc[mt][nt][1];
            y1[l]     = acc[mt][nt][2];
            y1[l + 1] = acc[mt][nt][3];
        }
    }
}

// ---------------- K2: attention per l-tile (LT=4) --------------------------
#define SP_STR 260
#define SX_STR 36
#define SV_STR 132
#define K2_SMEM ((64 * SP_STR + 64 * SV_STR) * 4)

__global__ __launch_bounds__(256, 2) void k2_attn(const float* __restrict__ x) {
    extern __shared__ float smemf[];
    float* sP = smemf;
    float* sX = smemf + 64 * SP_STR;
    float* sG = sX + 64 * SX_STR;
    float* sV = smemf + 64 * SP_STR;

    int tid = threadIdx.x;
    int lt  = blockIdx.x * LT;
    int tb  = tid & 15;
    int td  = tid >> 4;

    float acc[4][4][4];
#pragma unroll
    for (int i = 0; i < 4; i++)
#pragma unroll
        for (int j = 0; j < 4; j++)
#pragma unroll
            for (int l = 0; l < 4; l++) acc[i][j][l] = 0.f;

    for (int c0 = 0; c0 < NC; c0 += 8) {
#pragma unroll
        for (int j = 0; j < 2; j++) {
            int t  = tid + j * 256;
            int bb = t >> 3, cc = t & 7;
            *(float4*)&sX[bb * SX_STR + cc * 4] =
                *(const float4*)(x   + ((size_t)bb * NC + c0 + cc) * NL + lt);
            *(float4*)&sG[bb * SX_STR + cc * 4] =
                *(const float4*)(d_g + ((size_t)bb * NC + c0 + cc) * NL + lt);
        }
        __syncthreads();
#pragma unroll
        for (int cc = 0; cc < 8; cc++) {
            float4 xv[4], gv[4];
#pragma unroll
            for (int i = 0; i < 4; i++)
                xv[i] = *(float4*)&sX[(tb + 16 * i) * SX_STR + cc * 4];
#pragma unroll
            for (int i = 0; i < 4; i++)
                gv[i] = *(float4*)&sG[(td + 16 * i) * SX_STR + cc * 4];
#pragma unroll
            for (int bi = 0; bi < 4; bi++)
#pragma unroll
                for (int di = 0; di < 4; di++) {
                    acc[bi][di][0] += xv[bi].x * gv[di].x;
                    acc[bi][di][1] += xv[bi].y * gv[di].y;
                    acc[bi][di][2] += xv[bi].z * gv[di].z;
                    acc[bi][di][3] += xv[bi].w * gv[di].w;
                }
        }
        __syncthreads();
    }
#pragma unroll
    for (int bi = 0; bi < 4; bi++)
#pragma unroll
        for (int di = 0; di < 4; di++)
#pragma unroll
            for (int l = 0; l < 4; l++)
                sP[(tb + 16 * bi) * SP_STR + (td + 16 * di) * 4 + l] = acc[bi][di][l];
    __syncthreads();

    {
        int b = tid >> 2, l = tid & 3;
        float* row = sP + b * SP_STR + l;
        float mx = -1e30f;
#pragma unroll 8
        for (int d = 0; d < 64; d++) mx = fmaxf(mx, row[d * 4]);
        float s = 0.f;
#pragma unroll 8
        for (int d = 0; d < 64; d++) {
            float e = __expf(row[d * 4] - mx);
            row[d * 4] = e;
            s += e;
        }
        float inv = 1.f / s;
#pragma unroll 8
        for (int d = 0; d < 64; d++) row[d * 4] *= inv;
    }
    __syncthreads();

    int tc = tid >> 4;
    for (int c0 = 0; c0 < NC; c0 += 32) {
#pragma unroll
        for (int j = 0; j < 8; j++) {
            int t  = tid + j * 256;
            int dd = t >> 5, ci = t & 31;
            *(float4*)&sV[dd * SV_STR + ci * 4] =
                *(const float4*)(d_v + ((size_t)dd * NC + c0 + ci) * NL + lt);
        }
        __syncthreads();
        float a3[4][2][4];
#pragma unroll
        for (int i = 0; i < 4; i++)
#pragma unroll
            for (int j = 0; j < 2; j++)
#pragma unroll
                for (int l = 0; l < 4; l++) a3[i][j][l] = 0.f;
#pragma unroll 4
        for (int d = 0; d < 64; d++) {
            float4 p[4];
#pragma unroll
            for (int i = 0; i < 4; i++)
                p[i] = *(float4*)&sP[(tb + 16 * i) * SP_STR + d * 4];
            float4 vv[2];
#pragma unroll
            for (int i = 0; i < 2; i++)
                vv[i] = *(float4*)&sV[d * SV_STR + (tc + 16 * i) * 4];
#pragma unroll
            for (int bi = 0; bi < 4; bi++)
#pragma unroll
                for (int ci = 0; ci < 2; ci++) {
                    a3[bi][ci][0] += p[bi].x * vv[ci].x;
                    a3[bi][ci][1] += p[bi].y * vv[ci].y;
                    a3[bi][ci][2] += p[bi].z * vv[ci].z;
                    a3[bi][ci][3] += p[bi].w * vv[ci].w;
                }
        }
#pragma unroll
        for (int bi = 0; bi < 4; bi++)
#pragma unroll
            for (int ci = 0; ci < 2; ci++) {
                float4 o4 = make_float4(a3[bi][ci][0], a3[bi][ci][1],
                                        a3[bi][ci][2], a3[bi][ci][3]);
                *(float4*)(d_virt + ((size_t)(tb + 16 * bi) * NC + c0 + tc + 16 * ci) * NL + lt) = o4;
            }
        __syncthreads();
    }
}

// ---------------- K3: per-batch GroupNorm stats (deterministic) ------------
__global__ void k3_stats() {
    int b   = blockIdx.x;
    int tid = threadIdx.x;
    const float4* p = (const float4*)(d_virt + (size_t)b * NC * NL);
    float s = 0.f, q = 0.f;
    for (int j = 0; j < 1024; j++) {
        float4 v = p[tid + j * 256];
        s += v.x + v.y + v.z + v.w;
        q += v.x * v.x + v.y * v.y + v.z * v.z + v.w * v.w;
    }
    __shared__ float ss[256], sq[256];
    ss[tid] = s; sq[tid] = q;
    __syncthreads();
    for (int st = 128; st > 0; st >>= 1) {
        if (tid < st) { ss[tid] += ss[tid + st]; sq[tid] += sq[tid + st]; }
        __syncthreads();
    }
    if (tid == 0) {
        float N    = (float)(NC * NL);
        float mean = ss[0] / N;
        float var  = sq[0] / N - mean * mean;
        d_mean[b] = mean;
        d_rstd[b] = rsqrtf(var + 1e-5f);
    }
}

// ---------------- launch ----------------------------------------------------
extern "C" void kernel_launch(void* const* d_in, const int* in_sizes, int n_in,
                              void* d_out, int out_size) {
    const float* x     = (const float*)d_in[0];
    const float* Wq    = (const float*)d_in[1];
    const float* Wk    = (const float*)d_in[2];
    const float* Wv    = (const float*)d_in[3];
    const float* Wc    = (const float*)d_in[4];
    const float* Wout  = (const float*)d_in[5];
    const float* gamma = (const float*)d_in[6];
    const float* beta  = (const float*)d_in[7];
    float* out = (float*)d_out;

    cudaFuncSetAttribute(k2_attn, cudaFuncAttributeMaxDynamicSharedMemorySize, K2_SMEM);
    cudaFuncSetAttribute(k_gemm,  cudaFuncAttributeMaxDynamicSharedMemorySize, KG_SMEM);

    dim3 b16(16, 16);
    k0_M <<<dim3(16, 16), b16>>>(Wq, Wk);
    k0_W2<<<dim3(16, 16), b16>>>(Wout, Wc);
    kprep_A<<<512, 256>>>(Wv, Wout);
    kcvt_x<<<65536, 256>>>(x);

    k_gemm<<<dim3(4, NL / 128, NB), 256, KG_SMEM>>>(0, nullptr);

    k2_attn<<<NL / LT, 256, K2_SMEM>>>(x);
    k3_stats<<<NB, 256>>>();
    kcvt_v<<<65536, 256>>>(gamma, beta);

    k_gemm<<<dim3(2, NL / 128, NB), 256, KG_SMEM>>>(1, out);
}

// round 12
// speedup vs baseline: 1.4934x; 1.4934x over previous
#include <cuda_runtime.h>
#include <cuda_fp16.h>
#include <cstdint>
#include <cstddef>

#define NB 64
#define NC 256
#define NL 4096
#define LT 4

// ---------------- scratch (device globals; no allocation allowed) ----------
__device__ float d_M [NC * NC];                 // Wq^T Wk / sqrt(C)
__device__ float d_W2[NC * NC];                 // Wout @ Wc
__device__ float d_g   [(size_t)NB * NC * NL];  // M @ x
__device__ float d_v   [(size_t)NB * NC * NL];  // Wv @ x
__device__ float d_virt[(size_t)NB * NC * NL];  // attention output
__device__ float d_mean[NB];
__device__ float d_rstd[NB];

// ---------------- helpers ---------------------------------------------------
__device__ __forceinline__ void mma_f16(float* c, const uint32_t* a,
                                        const uint32_t* b) {
    asm volatile(
        "mma.sync.aligned.m16n8k16.row.col.f32.f16.f16.f32 "
        "{%0,%1,%2,%3}, {%4,%5,%6,%7}, {%8,%9}, {%0,%1,%2,%3};"
        : "+f"(c[0]), "+f"(c[1]), "+f"(c[2]), "+f"(c[3])
        : "r"(a[0]), "r"(a[1]), "r"(a[2]), "r"(a[3]), "r"(b[0]), "r"(b[1]));
}

// ---------------- K0: M = Wq^T Wk / 16 -------------------------------------
__global__ void k0_M(const float* __restrict__ Wq, const float* __restrict__ Wk) {
    __shared__ float sA[16][17], sB[16][17];
    int tx = threadIdx.x, ty = threadIdx.y;
    int c1 = blockIdx.y * 16 + ty;
    int c2 = blockIdx.x * 16 + tx;
    float acc = 0.f;
    for (int o0 = 0; o0 < NC; o0 += 16) {
        sA[ty][tx] = Wq[(o0 + ty) * NC + blockIdx.y * 16 + tx];
        sB[ty][tx] = Wk[(o0 + ty) * NC + blockIdx.x * 16 + tx];
        __syncthreads();
#pragma unroll
        for (int i = 0; i < 16; i++) acc += sA[i][ty] * sB[i][tx];
        __syncthreads();
    }
    d_M[c1 * NC + c2] = acc * 0.0625f;
}

// ---------------- K0b: W2 = Wout @ Wc --------------------------------------
__global__ void k0_W2(const float* __restrict__ Wout, const float* __restrict__ Wc) {
    __shared__ float sA[16][17], sB[16][17];
    int tx = threadIdx.x, ty = threadIdx.y;
    int o = blockIdx.y * 16 + ty;
    int c = blockIdx.x * 16 + tx;
    float acc = 0.f;
    for (int m0 = 0; m0 < NC; m0 += 16) {
        sA[ty][tx] = Wout[o * NC + m0 + tx];
        sB[ty][tx] = Wc[(m0 + ty) * NC + blockIdx.x * 16 + tx];
        __syncthreads();
#pragma unroll
        for (int i = 0; i < 16; i++) acc += sA[ty][i] * sB[i][tx];
        __syncthreads();
    }
    d_W2[o * NC + c] = acc;
}

// ---------------- FP16 tensor-core GEMM ------------------------------------
// mode 0: Y[512,L] = [M ; Wv] @ x[b]          -> d_g / d_v   (K = 256)
// mode 1: out[256,L] = [Wout|W2] @ [x ; relu(gn(virt))]      (K = 512)
// CTA tile 128(m) x 128(l), k-chunk 32, 8 warps (2m x 4n), warp tile 64x32.
// mma m16n8k16 f32.f16.f16.f32 (2 k16-steps per chunk).
__global__ __launch_bounds__(256, 2) void k_gemm(int mode, float* __restrict__ out,
                                                 const float* __restrict__ Wv,
                                                 const float* __restrict__ x,
                                                 const float* __restrict__ Wout,
                                                 const float* __restrict__ gamma,
                                                 const float* __restrict__ beta) {
    __shared__ __half  As[128][40];     // [m][k]   bank=(20g+tg)%32 bijective
    __shared__ __half2 Bs2[16][136];    // [k/2][l] half2=(k even,k odd); bank=(8tg+g)%32

    int tid = threadIdx.x;
    int b   = blockIdx.z;
    int l0  = blockIdx.y * 128;
    int m0  = blockIdx.x * 128;
    int KK  = mode ? 512 : 256;

    const float* Ag = nullptr;
    float* Ybase;
    int mbase;
    if (mode == 0) {
        if (m0 < 256) { Ag = d_M + (size_t)m0 * NC;         Ybase = d_g; mbase = m0; }
        else          { Ag = Wv  + (size_t)(m0 - 256) * NC; Ybase = d_v; mbase = m0 - 256; }
    } else {
        Ybase = out; mbase = m0;
    }

    float mn = 0.f, rs = 0.f;
    if (mode) { mn = d_mean[b]; rs = d_rstd[b]; }

    int lane = tid & 31, w = tid >> 5;
    int g = lane >> 2, tg = lane & 3;
    int wm = (w & 1) * 64, wn = (w >> 1) * 32;

    float acc[4][4][4];
#pragma unroll
    for (int mt = 0; mt < 4; mt++)
#pragma unroll
        for (int nt = 0; nt < 4; nt++)
#pragma unroll
            for (int i = 0; i < 4; i++) acc[mt][nt][i] = 0.f;

#pragma unroll 1
    for (int k0 = 0; k0 < KK; k0 += 32) {
        // ---- stage A chunk [128][32] -> fp16 ----
        const float* Asrc;
        int kc;
        if (mode == 0) { Asrc = Ag; kc = k0; }
        else {
            Asrc = ((k0 < 256) ? Wout : d_W2) + (size_t)m0 * NC;
            kc = k0 & 255;
        }
#pragma unroll
        for (int j = 0; j < 4; j++) {
            int f = tid + 256 * j;
            int r = f >> 3, s = f & 7;
            float4 a = *(const float4*)(Asrc + (size_t)r * NC + kc + s * 4);
            __half2 h0 = __floats2half2_rn(a.x, a.y);
            __half2 h1 = __floats2half2_rn(a.z, a.w);
            *(__half2*)&As[r][s * 4]     = h0;
            *(__half2*)&As[r][s * 4 + 2] = h1;
        }
        // ---- stage B chunk [32][128] -> fp16 k-pair half2 ----
        // Bs2[k2][l] = (B[2k2][l], B[2k2+1][l])
#pragma unroll
        for (int j = 0; j < 2; j++) {
            int f  = tid + 256 * j;
            int k2 = f >> 5, lg = f & 31;
            int kg = k0 + 2 * k2;
            int cl = lg * 4;
            float4 v0, v1;
            if (!mode || kg < 256) {
                v0 = *(const float4*)(x + ((size_t)b * NC + kg)     * NL + l0 + cl);
                v1 = *(const float4*)(x + ((size_t)b * NC + kg + 1) * NL + l0 + cl);
            } else {
                int c0 = kg - 256, c1 = c0 + 1;
                v0 = *(const float4*)(d_virt + ((size_t)b * NC + c0) * NL + l0 + cl);
                v1 = *(const float4*)(d_virt + ((size_t)b * NC + c1) * NL + l0 + cl);
                float g0 = gamma[c0] * rs, b0 = beta[c0] - mn * g0;
                float g1 = gamma[c1] * rs, b1 = beta[c1] - mn * g1;
                v0.x = fmaxf(fmaf(v0.x, g0, b0), 0.f);
                v0.y = fmaxf(fmaf(v0.y, g0, b0), 0.f);
                v0.z = fmaxf(fmaf(v0.z, g0, b0), 0.f);
                v0.w = fmaxf(fmaf(v0.w, g0, b0), 0.f);
                v1.x = fmaxf(fmaf(v1.x, g1, b1), 0.f);
                v1.y = fmaxf(fmaf(v1.y, g1, b1), 0.f);
                v1.z = fmaxf(fmaf(v1.z, g1, b1), 0.f);
                v1.w = fmaxf(fmaf(v1.w, g1, b1), 0.f);
            }
            Bs2[k2][cl]     = __floats2half2_rn(v0.x, v1.x);
            Bs2[k2][cl + 1] = __floats2half2_rn(v0.y, v1.y);
            Bs2[k2][cl + 2] = __floats2half2_rn(v0.z, v1.z);
            Bs2[k2][cl + 3] = __floats2half2_rn(v0.w, v1.w);
        }
        __syncthreads();

        // ---- compute: 2 k16-steps x 16 mma ----
#pragma unroll
        for (int ks = 0; ks < 2; ks++) {
            int kb = ks * 16;          // half index base
            int k2b = ks * 8;          // half2 row base
            uint32_t bf[4][2];
#pragma unroll
            for (int nt = 0; nt < 4; nt++) {
                int n = wn + nt * 8 + g;
                bf[nt][0] = *(uint32_t*)&Bs2[k2b + tg][n];
                bf[nt][1] = *(uint32_t*)&Bs2[k2b + tg + 4][n];
            }
            uint32_t af[4][4];
#pragma unroll
            for (int mt = 0; mt < 4; mt++) {
                int rb = wm + mt * 16;
                af[mt][0] = *(uint32_t*)&As[rb + g][kb + 2 * tg];
                af[mt][1] = *(uint32_t*)&As[rb + g + 8][kb + 2 * tg];
                af[mt][2] = *(uint32_t*)&As[rb + g][kb + 2 * tg + 8];
                af[mt][3] = *(uint32_t*)&As[rb + g + 8][kb + 2 * tg + 8];
            }
#pragma unroll
            for (int mt = 0; mt < 4; mt++)
#pragma unroll
                for (int nt = 0; nt < 4; nt++)
                    mma_f16(acc[mt][nt], af[mt], bf[nt]);
        }
        __syncthreads();
    }

    // ---- epilogue: fp32 stores ----
#pragma unroll
    for (int mt = 0; mt < 4; mt++) {
        int m = mbase + wm + mt * 16 + g;
        float* y0 = Ybase + ((size_t)b * NC + m) * NL + l0;
        float* y1 = Ybase + ((size_t)b * NC + m + 8) * NL + l0;
#pragma unroll
        for (int nt = 0; nt < 4; nt++) {
            int l = wn + nt * 8 + 2 * tg;
            y0[l]     = acc[mt][nt][0];
            y0[l + 1] = acc[mt][nt][1];
            y1[l]     = acc[mt][nt][2];
            y1[l + 1] = acc[mt][nt][3];
        }
    }
}

// ---------------- K2: attention per l-tile (LT=4) --------------------------
#define SP_STR 260
#define SX_STR 36
#define SV_STR 132
#define K2_SMEM ((64 * SP_STR + 64 * SV_STR) * 4)

__global__ __launch_bounds__(256, 2) void k2_attn(const float* __restrict__ x) {
    extern __shared__ float smemf[];
    float* sP = smemf;
    float* sX = smemf + 64 * SP_STR;
    float* sG = sX + 64 * SX_STR;
    float* sV = smemf + 64 * SP_STR;

    int tid = threadIdx.x;
    int lt  = blockIdx.x * LT;
    int tb  = tid & 15;
    int td  = tid >> 4;

    float acc[4][4][4];
#pragma unroll
    for (int i = 0; i < 4; i++)
#pragma unroll
        for (int j = 0; j < 4; j++)
#pragma unroll
            for (int l = 0; l < 4; l++) acc[i][j][l] = 0.f;

    for (int c0 = 0; c0 < NC; c0 += 8) {
#pragma unroll
        for (int j = 0; j < 2; j++) {
            int t  = tid + j * 256;
            int bb = t >> 3, cc = t & 7;
            *(float4*)&sX[bb * SX_STR + cc * 4] =
                *(const float4*)(x   + ((size_t)bb * NC + c0 + cc) * NL + lt);
            *(float4*)&sG[bb * SX_STR + cc * 4] =
                *(const float4*)(d_g + ((size_t)bb * NC + c0 + cc) * NL + lt);
        }
        __syncthreads();
#pragma unroll
        for (int cc = 0; cc < 8; cc++) {
            float4 xv[4], gv[4];
#pragma unroll
            for (int i = 0; i < 4; i++)
                xv[i] = *(float4*)&sX[(tb + 16 * i) * SX_STR + cc * 4];
#pragma unroll
            for (int i = 0; i < 4; i++)
                gv[i] = *(float4*)&sG[(td + 16 * i) * SX_STR + cc * 4];
#pragma unroll
            for (int bi = 0; bi < 4; bi++)
#pragma unroll
                for (int di = 0; di < 4; di++) {
                    acc[bi][di][0] += xv[bi].x * gv[di].x;
                    acc[bi][di][1] += xv[bi].y * gv[di].y;
                    acc[bi][di][2] += xv[bi].z * gv[di].z;
                    acc[bi][di][3] += xv[bi].w * gv[di].w;
                }
        }
        __syncthreads();
    }
#pragma unroll
    for (int bi = 0; bi < 4; bi++)
#pragma unroll
        for (int di = 0; di < 4; di++)
#pragma unroll
            for (int l = 0; l < 4; l++)
                sP[(tb + 16 * bi) * SP_STR + (td + 16 * di) * 4 + l] = acc[bi][di][l];
    __syncthreads();

    {
        int b = tid >> 2, l = tid & 3;
        float* row = sP + b * SP_STR + l;
        float mx = -1e30f;
#pragma unroll 8
        for (int d = 0; d < 64; d++) mx = fmaxf(mx, row[d * 4]);
        float s = 0.f;
#pragma unroll 8
        for (int d = 0; d < 64; d++) {
            float e = __expf(row[d * 4] - mx);
            row[d * 4] = e;
            s += e;
        }
        float inv = 1.f / s;
#pragma unroll 8
        for (int d = 0; d < 64; d++) row[d * 4] *= inv;
    }
    __syncthreads();

    int tc = tid >> 4;
    for (int c0 = 0; c0 < NC; c0 += 32) {
#pragma unroll
        for (int j = 0; j < 8; j++) {
            int t  = tid + j * 256;
            int dd = t >> 5, ci = t & 31;
            *(float4*)&sV[dd * SV_STR + ci * 4] =
                *(const float4*)(d_v + ((size_t)dd * NC + c0 + ci) * NL + lt);
        }
        __syncthreads();
        float a3[4][2][4];
#pragma unroll
        for (int i = 0; i < 4; i++)
#pragma unroll
            for (int j = 0; j < 2; j++)
#pragma unroll
                for (int l = 0; l < 4; l++) a3[i][j][l] = 0.f;
#pragma unroll 4
        for (int d = 0; d < 64; d++) {
            float4 p[4];
#pragma unroll
            for (int i = 0; i < 4; i++)
                p[i] = *(float4*)&sP[(tb + 16 * i) * SP_STR + d * 4];
            float4 vv[2];
#pragma unroll
            for (int i = 0; i < 2; i++)
                vv[i] = *(float4*)&sV[d * SV_STR + (tc + 16 * i) * 4];
#pragma unroll
            for (int bi = 0; bi < 4; bi++)
#pragma unroll
                for (int ci = 0; ci < 2; ci++) {
                    a3[bi][ci][0] += p[bi].x * vv[ci].x;
                    a3[bi][ci][1] += p[bi].y * vv[ci].y;
                    a3[bi][ci][2] += p[bi].z * vv[ci].z;
                    a3[bi][ci][3] += p[bi].w * vv[ci].w;
                }
        }
#pragma unroll
        for (int bi = 0; bi < 4; bi++)
#pragma unroll
            for (int ci = 0; ci < 2; ci++) {
                float4 o4 = make_float4(a3[bi][ci][0], a3[bi][ci][1],
                                        a3[bi][ci][2], a3[bi][ci][3]);
                *(float4*)(d_virt + ((size_t)(tb + 16 * bi) * NC + c0 + tc + 16 * ci) * NL + lt) = o4;
            }
        __syncthreads();
    }
}

// ---------------- K3: per-batch GroupNorm stats (deterministic) ------------
__global__ void k3_stats() {
    int b   = blockIdx.x;
    int tid = threadIdx.x;
    const float4* p = (const float4*)(d_virt + (size_t)b * NC * NL);
    float s = 0.f, q = 0.f;
    for (int j = 0; j < 1024; j++) {
        float4 v = p[tid + j * 256];
        s += v.x + v.y + v.z + v.w;
        q += v.x * v.x + v.y * v.y + v.z * v.z + v.w * v.w;
    }
    __shared__ float ss[256], sq[256];
    ss[tid] = s; sq[tid] = q;
    __syncthreads();
    for (int st = 128; st > 0; st >>= 1) {
        if (tid < st) { ss[tid] += ss[tid + st]; sq[tid] += sq[tid + st]; }
        __syncthreads();
    }
    if (tid == 0) {
        float N    = (float)(NC * NL);
        float mean = ss[0] / N;
        float var  = sq[0] / N - mean * mean;
        d_mean[b] = mean;
        d_rstd[b] = rsqrtf(var + 1e-5f);
    }
}

// ---------------- launch ----------------------------------------------------
extern "C" void kernel_launch(void* const* d_in, const int* in_sizes, int n_in,
                              void* d_out, int out_size) {
    const float* x     = (const float*)d_in[0];
    const float* Wq    = (const float*)d_in[1];
    const float* Wk    = (const float*)d_in[2];
    const float* Wv    = (const float*)d_in[3];
    const float* Wc    = (const float*)d_in[4];
    const float* Wout  = (const float*)d_in[5];
    const float* gamma = (const float*)d_in[6];
    const float* beta  = (const float*)d_in[7];
    float* out = (float*)d_out;

    cudaFuncSetAttribute(k2_attn, cudaFuncAttributeMaxDynamicSharedMemorySize, K2_SMEM);

    dim3 b16(16, 16);
    k0_M <<<dim3(16, 16), b16>>>(Wq, Wk);
    k0_W2<<<dim3(16, 16), b16>>>(Wout, Wc);

    k_gemm<<<dim3(4, NL / 128, NB), 256>>>(0, nullptr, Wv, x, Wout, gamma, beta);

    k2_attn<<<NL / LT, 256, K2_SMEM>>>(x);
    k3_stats<<<NB, 256>>>();

    k_gemm<<<dim3(2, NL / 128, NB), 256>>>(1, out, Wv, x, Wout, gamma, beta);
}

// round 13
// speedup vs baseline: 1.6737x; 1.1207x over previous
#include <cuda_runtime.h>
#include <cuda_fp16.h>
#include <cstdint>
#include <cstddef>

#define NB 64
#define NC 256
#define NL 4096
#define LT 4

// ---------------- scratch (device globals; no allocation allowed) ----------
__device__ float d_M [NC * NC];                 // Wq^T Wk / sqrt(C)
__device__ float d_W2[NC * NC];                 // Wout @ Wc
__device__ float d_g   [(size_t)NB * NC * NL];  // M @ x
__device__ float d_v   [(size_t)NB * NC * NL];  // Wv @ x
__device__ float d_virt[(size_t)NB * NC * NL];  // attention output
__device__ float d_mean[NB];
__device__ float d_rstd[NB];

// ---------------- helpers ---------------------------------------------------
__device__ __forceinline__ void mma_f16(float* c, const uint32_t* a,
                                        const uint32_t* b) {
    asm volatile(
        "mma.sync.aligned.m16n8k16.row.col.f32.f16.f16.f32 "
        "{%0,%1,%2,%3}, {%4,%5,%6,%7}, {%8,%9}, {%0,%1,%2,%3};"
        : "+f"(c[0]), "+f"(c[1]), "+f"(c[2]), "+f"(c[3])
        : "r"(a[0]), "r"(a[1]), "r"(a[2]), "r"(a[3]), "r"(b[0]), "r"(b[1]));
}

// ---------------- K0: M = Wq^T Wk / 16 -------------------------------------
__global__ void k0_M(const float* __restrict__ Wq, const float* __restrict__ Wk) {
    __shared__ float sA[16][17], sB[16][17];
    int tx = threadIdx.x, ty = threadIdx.y;
    int c1 = blockIdx.y * 16 + ty;
    int c2 = blockIdx.x * 16 + tx;
    float acc = 0.f;
    for (int o0 = 0; o0 < NC; o0 += 16) {
        sA[ty][tx] = Wq[(o0 + ty) * NC + blockIdx.y * 16 + tx];
        sB[ty][tx] = Wk[(o0 + ty) * NC + blockIdx.x * 16 + tx];
        __syncthreads();
#pragma unroll
        for (int i = 0; i < 16; i++) acc += sA[i][ty] * sB[i][tx];
        __syncthreads();
    }
    d_M[c1 * NC + c2] = acc * 0.0625f;
}

// ---------------- K0b: W2 = Wout @ Wc --------------------------------------
__global__ void k0_W2(const float* __restrict__ Wout, const float* __restrict__ Wc) {
    __shared__ float sA[16][17], sB[16][17];
    int tx = threadIdx.x, ty = threadIdx.y;
    int o = blockIdx.y * 16 + ty;
    int c = blockIdx.x * 16 + tx;
    float acc = 0.f;
    for (int m0 = 0; m0 < NC; m0 += 16) {
        sA[ty][tx] = Wout[o * NC + m0 + tx];
        sB[ty][tx] = Wc[(m0 + ty) * NC + blockIdx.x * 16 + tx];
        __syncthreads();
#pragma unroll
        for (int i = 0; i < 16; i++) acc += sA[ty][i] * sB[i][tx];
        __syncthreads();
    }
    d_W2[o * NC + c] = acc;
}

// ---------------- FP16 tensor-core GEMM (B register-prefetch) ---------------
// mode 0: Y[512,L] = [M ; Wv] @ x[b]          -> d_g / d_v   (K = 256)
// mode 1: out[256,L] = [Wout|W2] @ [x ; relu(gn(virt))]      (K = 512)
// CTA tile 128(m) x 128(l), k-chunk 32, 8 warps (2m x 4n), warp tile 64x32.
// B chunk for iteration i+1 is prefetched into registers during compute of i.
__global__ __launch_bounds__(256, 2) void k_gemm(int mode, float* __restrict__ out,
                                                 const float* __restrict__ Wv,
                                                 const float* __restrict__ x,
                                                 const float* __restrict__ Wout,
                                                 const float* __restrict__ gamma,
                                                 const float* __restrict__ beta) {
    __shared__ __half  As[128][40];     // [m][k]   bank=(20g+tg)%32 bijective
    __shared__ __half2 Bs2[16][136];    // [k/2][l] half2=(k even,k odd); bank=(8tg+g)%32

    int tid = threadIdx.x;
    int b   = blockIdx.z;
    int l0  = blockIdx.y * 128;
    int m0  = blockIdx.x * 128;
    int KK  = mode ? 512 : 256;

    const float* Ag = nullptr;
    float* Ybase;
    int mbase;
    if (mode == 0) {
        if (m0 < 256) { Ag = d_M + (size_t)m0 * NC;         Ybase = d_g; mbase = m0; }
        else          { Ag = Wv  + (size_t)(m0 - 256) * NC; Ybase = d_v; mbase = m0 - 256; }
    } else {
        Ybase = out; mbase = m0;
    }

    float mn = 0.f, rs = 0.f;
    if (mode) { mn = d_mean[b]; rs = d_rstd[b]; }

    int lane = tid & 31, w = tid >> 5;
    int g = lane >> 2, tg = lane & 3;
    int wm = (w & 1) * 64, wn = (w >> 1) * 32;

    float acc[4][4][4];
#pragma unroll
    for (int mt = 0; mt < 4; mt++)
#pragma unroll
        for (int nt = 0; nt < 4; nt++)
#pragma unroll
            for (int i = 0; i < 4; i++) acc[mt][nt][i] = 0.f;

    // per-thread B staging coordinates (fixed across chunks)
    int f0 = tid,        k2_0 = f0 >> 5, cl0 = (f0 & 31) * 4;
    int f1 = tid + 256,  k2_1 = f1 >> 5, cl1 = (f1 & 31) * 4;

    // ---- prefetch B chunk 0 (always from x) ----
    float4 pb[4];
    {
        const float* B0 = x + ((size_t)b * NC + 2 * k2_0) * NL + l0 + cl0;
        const float* B1 = x + ((size_t)b * NC + 2 * k2_1) * NL + l0 + cl1;
        pb[0] = *(const float4*)B0;
        pb[1] = *(const float4*)(B0 + NL);
        pb[2] = *(const float4*)B1;
        pb[3] = *(const float4*)(B1 + NL);
    }

#pragma unroll 1
    for (int k0 = 0; k0 < KK; k0 += 32) {
        // ---- stage A chunk [128][32] -> fp16 ----
        const float* Asrc;
        int kc;
        if (mode == 0) { Asrc = Ag; kc = k0; }
        else {
            Asrc = ((k0 < 256) ? Wout : d_W2) + (size_t)m0 * NC;
            kc = k0 & 255;
        }
#pragma unroll
        for (int j = 0; j < 4; j++) {
            int f = tid + 256 * j;
            int r = f >> 3, s = f & 7;
            float4 a = *(const float4*)(Asrc + (size_t)r * NC + kc + s * 4);
            __half2 h0 = __floats2half2_rn(a.x, a.y);
            __half2 h1 = __floats2half2_rn(a.z, a.w);
            *(__half2*)&As[r][s * 4]     = h0;
            *(__half2*)&As[r][s * 4 + 2] = h1;
        }
        // ---- stage B chunk from prefetch regs (apply gn+relu if needed) ----
#pragma unroll
        for (int j = 0; j < 2; j++) {
            int k2 = j ? k2_1 : k2_0;
            int cl = j ? cl1 : cl0;
            int kg = k0 + 2 * k2;
            float4 v0 = pb[2 * j], v1 = pb[2 * j + 1];
            if (mode && kg >= 256) {
                int c0 = kg - 256, c1 = c0 + 1;
                float g0 = gamma[c0] * rs, b0 = beta[c0] - mn * g0;
                float g1 = gamma[c1] * rs, b1 = beta[c1] - mn * g1;
                v0.x = fmaxf(fmaf(v0.x, g0, b0), 0.f);
                v0.y = fmaxf(fmaf(v0.y, g0, b0), 0.f);
                v0.z = fmaxf(fmaf(v0.z, g0, b0), 0.f);
                v0.w = fmaxf(fmaf(v0.w, g0, b0), 0.f);
                v1.x = fmaxf(fmaf(v1.x, g1, b1), 0.f);
                v1.y = fmaxf(fmaf(v1.y, g1, b1), 0.f);
                v1.z = fmaxf(fmaf(v1.z, g1, b1), 0.f);
                v1.w = fmaxf(fmaf(v1.w, g1, b1), 0.f);
            }
            Bs2[k2][cl]     = __floats2half2_rn(v0.x, v1.x);
            Bs2[k2][cl + 1] = __floats2half2_rn(v0.y, v1.y);
            Bs2[k2][cl + 2] = __floats2half2_rn(v0.z, v1.z);
            Bs2[k2][cl + 3] = __floats2half2_rn(v0.w, v1.w);
        }
        __syncthreads();

        // ---- issue prefetch for next chunk (latency overlaps compute) ----
        if (k0 + 32 < KK) {
            int kn = k0 + 32;
            int kg0 = kn + 2 * k2_0;
            int kg1 = kn + 2 * k2_1;
            const float* B0 = (!mode || kg0 < 256)
                ? x      + ((size_t)b * NC + kg0)         * NL + l0 + cl0
                : d_virt + ((size_t)b * NC + (kg0 - 256)) * NL + l0 + cl0;
            const float* B1 = (!mode || kg1 < 256)
                ? x      + ((size_t)b * NC + kg1)         * NL + l0 + cl1
                : d_virt + ((size_t)b * NC + (kg1 - 256)) * NL + l0 + cl1;
            pb[0] = *(const float4*)B0;
            pb[1] = *(const float4*)(B0 + NL);
            pb[2] = *(const float4*)B1;
            pb[3] = *(const float4*)(B1 + NL);
        }

        // ---- compute: 2 k16-steps x 16 mma ----
#pragma unroll
        for (int ks = 0; ks < 2; ks++) {
            int kb = ks * 16;          // half index base
            int k2b = ks * 8;          // half2 row base
            uint32_t bf[4][2];
#pragma unroll
            for (int nt = 0; nt < 4; nt++) {
                int n = wn + nt * 8 + g;
                bf[nt][0] = *(uint32_t*)&Bs2[k2b + tg][n];
                bf[nt][1] = *(uint32_t*)&Bs2[k2b + tg + 4][n];
            }
            uint32_t af[4][4];
#pragma unroll
            for (int mt = 0; mt < 4; mt++) {
                int rb = wm + mt * 16;
                af[mt][0] = *(uint32_t*)&As[rb + g][kb + 2 * tg];
                af[mt][1] = *(uint32_t*)&As[rb + g + 8][kb + 2 * tg];
                af[mt][2] = *(uint32_t*)&As[rb + g][kb + 2 * tg + 8];
                af[mt][3] = *(uint32_t*)&As[rb + g + 8][kb + 2 * tg + 8];
            }
#pragma unroll
            for (int mt = 0; mt < 4; mt++)
#pragma unroll
                for (int nt = 0; nt < 4; nt++)
                    mma_f16(acc[mt][nt], af[mt], bf[nt]);
        }
        __syncthreads();
    }

    // ---- epilogue: fp32 stores ----
#pragma unroll
    for (int mt = 0; mt < 4; mt++) {
        int m = mbase + wm + mt * 16 + g;
        float* y0 = Ybase + ((size_t)b * NC + m) * NL + l0;
        float* y1 = Ybase + ((size_t)b * NC + m + 8) * NL + l0;
#pragma unroll
        for (int nt = 0; nt < 4; nt++) {
            int l = wn + nt * 8 + 2 * tg;
            y0[l]     = acc[mt][nt][0];
            y0[l + 1] = acc[mt][nt][1];
            y1[l]     = acc[mt][nt][2];
            y1[l + 1] = acc[mt][nt][3];
        }
    }
}

// ---------------- K2: attention per l-tile (LT=4) --------------------------
#define SP_STR 260
#define SX_STR 36
#define SV_STR 132
#define K2_SMEM ((64 * SP_STR + 64 * SV_STR) * 4)

__global__ __launch_bounds__(256, 2) void k2_attn(const float* __restrict__ x) {
    extern __shared__ float smemf[];
    float* sP = smemf;
    float* sX = smemf + 64 * SP_STR;
    float* sG = sX + 64 * SX_STR;
    float* sV = smemf + 64 * SP_STR;

    int tid = threadIdx.x;
    int lt  = blockIdx.x * LT;
    int tb  = tid & 15;
    int td  = tid >> 4;

    float acc[4][4][4];
#pragma unroll
    for (int i = 0; i < 4; i++)
#pragma unroll
        for (int j = 0; j < 4; j++)
#pragma unroll
            for (int l = 0; l < 4; l++) acc[i][j][l] = 0.f;

    for (int c0 = 0; c0 < NC; c0 += 8) {
#pragma unroll
        for (int j = 0; j < 2; j++) {
            int t  = tid + j * 256;
            int bb = t >> 3, cc = t & 7;
            *(float4*)&sX[bb * SX_STR + cc * 4] =
                *(const float4*)(x   + ((size_t)bb * NC + c0 + cc) * NL + lt);
            *(float4*)&sG[bb * SX_STR + cc * 4] =
                *(const float4*)(d_g + ((size_t)bb * NC + c0 + cc) * NL + lt);
        }
        __syncthreads();
#pragma unroll
        for (int cc = 0; cc < 8; cc++) {
            float4 xv[4], gv[4];
#pragma unroll
            for (int i = 0; i < 4; i++)
                xv[i] = *(float4*)&sX[(tb + 16 * i) * SX_STR + cc * 4];
#pragma unroll
            for (int i = 0; i < 4; i++)
                gv[i] = *(float4*)&sG[(td + 16 * i) * SX_STR + cc * 4];
#pragma unroll
            for (int bi = 0; bi < 4; bi++)
#pragma unroll
                for (int di = 0; di < 4; di++) {
                    acc[bi][di][0] += xv[bi].x * gv[di].x;
                    acc[bi][di][1] += xv[bi].y * gv[di].y;
                    acc[bi][di][2] += xv[bi].z * gv[di].z;
                    acc[bi][di][3] += xv[bi].w * gv[di].w;
                }
        }
        __syncthreads();
    }
#pragma unroll
    for (int bi = 0; bi < 4; bi++)
#pragma unroll
        for (int di = 0; di < 4; di++)
#pragma unroll
            for (int l = 0; l < 4; l++)
                sP[(tb + 16 * bi) * SP_STR + (td + 16 * di) * 4 + l] = acc[bi][di][l];
    __syncthreads();

    {
        int b = tid >> 2, l = tid & 3;
        float* row = sP + b * SP_STR + l;
        float mx = -1e30f;
#pragma unroll 8
        for (int d = 0; d < 64; d++) mx = fmaxf(mx, row[d * 4]);
        float s = 0.f;
#pragma unroll 8
        for (int d = 0; d < 64; d++) {
            float e = __expf(row[d * 4] - mx);
            row[d * 4] = e;
            s += e;
        }
        float inv = 1.f / s;
#pragma unroll 8
        for (int d = 0; d < 64; d++) row[d * 4] *= inv;
    }
    __syncthreads();

    int tc = tid >> 4;
    for (int c0 = 0; c0 < NC; c0 += 32) {
#pragma unroll
        for (int j = 0; j < 8; j++) {
            int t  = tid + j * 256;
            int dd = t >> 5, ci = t & 31;
            *(float4*)&sV[dd * SV_STR + ci * 4] =
                *(const float4*)(d_v + ((size_t)dd * NC + c0 + ci) * NL + lt);
        }
        __syncthreads();
        float a3[4][2][4];
#pragma unroll
        for (int i = 0; i < 4; i++)
#pragma unroll
            for (int j = 0; j < 2; j++)
#pragma unroll
                for (int l = 0; l < 4; l++) a3[i][j][l] = 0.f;
#pragma unroll 4
        for (int d = 0; d < 64; d++) {
            float4 p[4];
#pragma unroll
            for (int i = 0; i < 4; i++)
                p[i] = *(float4*)&sP[(tb + 16 * i) * SP_STR + d * 4];
            float4 vv[2];
#pragma unroll
            for (int i = 0; i < 2; i++)
                vv[i] = *(float4*)&sV[d * SV_STR + (tc + 16 * i) * 4];
#pragma unroll
            for (int bi = 0; bi < 4; bi++)
#pragma unroll
                for (int ci = 0; ci < 2; ci++) {
                    a3[bi][ci][0] += p[bi].x * vv[ci].x;
                    a3[bi][ci][1] += p[bi].y * vv[ci].y;
                    a3[bi][ci][2] += p[bi].z * vv[ci].z;
                    a3[bi][ci][3] += p[bi].w * vv[ci].w;
                }
        }
#pragma unroll
        for (int bi = 0; bi < 4; bi++)
#pragma unroll
            for (int ci = 0; ci < 2; ci++) {
                float4 o4 = make_float4(a3[bi][ci][0], a3[bi][ci][1],
                                        a3[bi][ci][2], a3[bi][ci][3]);
                *(float4*)(d_virt + ((size_t)(tb + 16 * bi) * NC + c0 + tc + 16 * ci) * NL + lt) = o4;
            }
        __syncthreads();
    }
}

// ---------------- K3: per-batch GroupNorm stats (deterministic) ------------
__global__ void k3_stats() {
    int b   = blockIdx.x;
    int tid = threadIdx.x;
    const float4* p = (const float4*)(d_virt + (size_t)b * NC * NL);
    float s = 0.f, q = 0.f;
    for (int j = 0; j < 1024; j++) {
        float4 v = p[tid + j * 256];
        s += v.x + v.y + v.z + v.w;
        q += v.x * v.x + v.y * v.y + v.z * v.z + v.w * v.w;
    }
    __shared__ float ss[256], sq[256];
    ss[tid] = s; sq[tid] = q;
    __syncthreads();
    for (int st = 128; st > 0; st >>= 1) {
        if (tid < st) { ss[tid] += ss[tid + st]; sq[tid] += sq[tid + st]; }
        __syncthreads();
    }
    if (tid == 0) {
        float N    = (float)(NC * NL);
        float mean = ss[0] / N;
        float var  = sq[0] / N - mean * mean;
        d_mean[b] = mean;
        d_rstd[b] = rsqrtf(var + 1e-5f);
    }
}

// ---------------- launch ----------------------------------------------------
extern "C" void kernel_launch(void* const* d_in, const int* in_sizes, int n_in,
                              void* d_out, int out_size) {
    const float* x     = (const float*)d_in[0];
    const float* Wq    = (const float*)d_in[1];
    const float* Wk    = (const float*)d_in[2];
    const float* Wv    = (const float*)d_in[3];
    const float* Wc    = (const float*)d_in[4];
    const float* Wout  = (const float*)d_in[5];
    const float* gamma = (const float*)d_in[6];
    const float* beta  = (const float*)d_in[7];
    float* out = (float*)d_out;

    cudaFuncSetAttribute(k2_attn, cudaFuncAttributeMaxDynamicSharedMemorySize, K2_SMEM);

    dim3 b16(16, 16);
    k0_M <<<dim3(16, 16), b16>>>(Wq, Wk);
    k0_W2<<<dim3(16, 16), b16>>>(Wout, Wc);

    k_gemm<<<dim3(4, NL / 128, NB), 256>>>(0, nullptr, Wv, x, Wout, gamma, beta);

    k2_attn<<<NL / LT, 256, K2_SMEM>>>(x);
    k3_stats<<<NB, 256>>>();

    k_gemm<<<dim3(2, NL / 128, NB), 256>>>(1, out, Wv, x, Wout, gamma, beta);
}

// round 14
// speedup vs baseline: 1.6821x; 1.0050x over previous
#include <cuda_runtime.h>
#include <cuda_fp16.h>
#include <cstdint>
#include <cstddef>

#define NB 64
#define NC 256
#define NL 4096
#define LT 4

// ---------------- scratch (device globals; no allocation allowed) ----------
__device__ float d_M [NC * NC];                 // Wq^T Wk / sqrt(C)
__device__ float d_W2[NC * NC];                 // Wout @ Wc
__device__ float d_g   [(size_t)NB * NC * NL];  // M @ x
__device__ float d_v   [(size_t)NB * NC * NL];  // Wv @ x
__device__ float d_virt[(size_t)NB * NC * NL];  // attention output
__device__ float d_mean[NB];
__device__ float d_rstd[NB];
__device__ __half d_A0h[512 * 256];             // fp16([M ; Wv])
__device__ __half d_A1h[256 * 512];             // fp16([Wout | W2])

// ---------------- helpers ---------------------------------------------------
__device__ __forceinline__ void mma_f16(float* c, const uint32_t* a,
                                        const uint32_t* b) {
    asm volatile(
        "mma.sync.aligned.m16n8k16.row.col.f32.f16.f16.f32 "
        "{%0,%1,%2,%3}, {%4,%5,%6,%7}, {%8,%9}, {%0,%1,%2,%3};"
        : "+f"(c[0]), "+f"(c[1]), "+f"(c[2]), "+f"(c[3])
        : "r"(a[0]), "r"(a[1]), "r"(a[2]), "r"(a[3]), "r"(b[0]), "r"(b[1]));
}

// ---------------- K0: M = Wq^T Wk / 16 -------------------------------------
__global__ void k0_M(const float* __restrict__ Wq, const float* __restrict__ Wk) {
    __shared__ float sA[16][17], sB[16][17];
    int tx = threadIdx.x, ty = threadIdx.y;
    int c1 = blockIdx.y * 16 + ty;
    int c2 = blockIdx.x * 16 + tx;
    float acc = 0.f;
    for (int o0 = 0; o0 < NC; o0 += 16) {
        sA[ty][tx] = Wq[(o0 + ty) * NC + blockIdx.y * 16 + tx];
        sB[ty][tx] = Wk[(o0 + ty) * NC + blockIdx.x * 16 + tx];
        __syncthreads();
#pragma unroll
        for (int i = 0; i < 16; i++) acc += sA[i][ty] * sB[i][tx];
        __syncthreads();
    }
    d_M[c1 * NC + c2] = acc * 0.0625f;
}

// ---------------- K0b: W2 = Wout @ Wc --------------------------------------
__global__ void k0_W2(const float* __restrict__ Wout, const float* __restrict__ Wc) {
    __shared__ float sA[16][17], sB[16][17];
    int tx = threadIdx.x, ty = threadIdx.y;
    int o = blockIdx.y * 16 + ty;
    int c = blockIdx.x * 16 + tx;
    float acc = 0.f;
    for (int m0 = 0; m0 < NC; m0 += 16) {
        sA[ty][tx] = Wout[o * NC + m0 + tx];
        sB[ty][tx] = Wc[(m0 + ty) * NC + blockIdx.x * 16 + tx];
        __syncthreads();
#pragma unroll
        for (int i = 0; i < 16; i++) acc += sA[ty][i] * sB[i][tx];
        __syncthreads();
    }
    d_W2[o * NC + c] = acc;
}

// ---------------- prepass: A matrices -> fp16 --------------------------------
__global__ void kprep_Ah(const float* __restrict__ Wv, const float* __restrict__ Wout) {
    int i = blockIdx.x * 256 + threadIdx.x;          // 0..131071
    d_A0h[i] = __float2half((i < 65536) ? d_M[i] : Wv[i - 65536]);
    int r = i >> 9, k = i & 511;
    d_A1h[i] = __float2half((k < 256) ? Wout[r * 256 + k] : d_W2[r * 256 + (k - 256)]);
}

// ---------------- FP16 tensor-core GEMM (A+B reg prefetch, dbl-buffer) ------
// mode 0: Y[512,L] = [M ; Wv] @ x[b]          -> d_g / d_v   (K = 256)
// mode 1: out[256,L] = [Wout|W2] @ [x ; relu(gn(virt))]      (K = 512)
// CTA tile 128(m) x 128(l), k-chunk 32, 8 warps (2m x 4n), warp tile 64x32.
// Both operand chunks for iteration i+1 are prefetched into registers during
// compute of i; smem is double-buffered -> ONE __syncthreads per chunk.
__global__ __launch_bounds__(256, 2) void k_gemm(int mode, float* __restrict__ out,
                                                 const float* __restrict__ x,
                                                 const float* __restrict__ gamma,
                                                 const float* __restrict__ beta) {
    __shared__ __half  As[2][128][40];   // bank=(20g+tg)%32 bijective
    __shared__ __half2 Bs2[2][16][136];  // half2=(k even,k odd); bank=(8tg+g)%32

    int tid = threadIdx.x;
    int b   = blockIdx.z;
    int l0  = blockIdx.y * 128;
    int m0  = blockIdx.x * 128;
    int nch = mode ? 16 : 8;
    int Kst = mode ? 512 : 256;
    const __half* Ah = (mode ? d_A1h : d_A0h) + (size_t)m0 * Kst;

    float* Ybase;
    int mbase;
    if (mode == 0) {
        if (m0 < 256) { Ybase = d_g; mbase = m0; }
        else          { Ybase = d_v; mbase = m0 - 256; }
    } else {
        Ybase = out; mbase = m0;
    }

    float mn = 0.f, rs = 0.f;
    if (mode) { mn = d_mean[b]; rs = d_rstd[b]; }

    int lane = tid & 31, w = tid >> 5;
    int g = lane >> 2, tg = lane & 3;
    int wm = (w & 1) * 64, wn = (w >> 1) * 32;

    float acc[4][4][4];
#pragma unroll
    for (int mt = 0; mt < 4; mt++)
#pragma unroll
        for (int nt = 0; nt < 4; nt++)
#pragma unroll
            for (int i = 0; i < 4; i++) acc[mt][nt][i] = 0.f;

    // per-thread staging coordinates (fixed across chunks)
    int ar0 = tid >> 2,         as0 = (tid & 3) * 8;          // A: f = tid
    int ar1 = (tid + 256) >> 2, as1 = (tid & 3) * 8;          // A: f = tid+256
    int k2_0 = tid >> 5,        cl0 = (tid & 31) * 4;         // B: f = tid
    int k2_1 = (tid + 256) >> 5, cl1 = (tid & 31) * 4;        // B: f = tid+256

    // ---- prefetch chunk 0 ----
    uint4  pa[2];
    float4 pb[4];
    pa[0] = *(const uint4*)(Ah + (size_t)ar0 * Kst + as0);
    pa[1] = *(const uint4*)(Ah + (size_t)ar1 * Kst + as1);
    {
        const float* B0 = x + ((size_t)b * NC + 2 * k2_0) * NL + l0 + cl0;
        const float* B1 = x + ((size_t)b * NC + 2 * k2_1) * NL + l0 + cl1;
        pb[0] = *(const float4*)B0;
        pb[1] = *(const float4*)(B0 + NL);
        pb[2] = *(const float4*)B1;
        pb[3] = *(const float4*)(B1 + NL);
    }

#pragma unroll 1
    for (int ch = 0; ch < nch; ch++) {
        int st = ch & 1;
        int k0 = ch * 32;
        // ---- stage A from regs ----
        *(uint4*)&As[st][ar0][as0] = pa[0];
        *(uint4*)&As[st][ar1][as1] = pa[1];
        // ---- stage B from regs (cvt + optional gn/relu) ----
#pragma unroll
        for (int j = 0; j < 2; j++) {
            int k2 = j ? k2_1 : k2_0;
            int cl = j ? cl1 : cl0;
            int kg = k0 + 2 * k2;
            float4 v0 = pb[2 * j], v1 = pb[2 * j + 1];
            if (mode && kg >= 256) {
                int c0 = kg - 256, c1 = c0 + 1;
                float g0 = gamma[c0] * rs, b0 = beta[c0] - mn * g0;
                float g1 = gamma[c1] * rs, b1 = beta[c1] - mn * g1;
                v0.x = fmaxf(fmaf(v0.x, g0, b0), 0.f);
                v0.y = fmaxf(fmaf(v0.y, g0, b0), 0.f);
                v0.z = fmaxf(fmaf(v0.z, g0, b0), 0.f);
                v0.w = fmaxf(fmaf(v0.w, g0, b0), 0.f);
                v1.x = fmaxf(fmaf(v1.x, g1, b1), 0.f);
                v1.y = fmaxf(fmaf(v1.y, g1, b1), 0.f);
                v1.z = fmaxf(fmaf(v1.z, g1, b1), 0.f);
                v1.w = fmaxf(fmaf(v1.w, g1, b1), 0.f);
            }
            Bs2[st][k2][cl]     = __floats2half2_rn(v0.x, v1.x);
            Bs2[st][k2][cl + 1] = __floats2half2_rn(v0.y, v1.y);
            Bs2[st][k2][cl + 2] = __floats2half2_rn(v0.z, v1.z);
            Bs2[st][k2][cl + 3] = __floats2half2_rn(v0.w, v1.w);
        }
        __syncthreads();

        // ---- issue prefetch for next chunk (latency overlaps compute) ----
        if (ch + 1 < nch) {
            int kn = (ch + 1) * 32;
            pa[0] = *(const uint4*)(Ah + (size_t)ar0 * Kst + kn + as0);
            pa[1] = *(const uint4*)(Ah + (size_t)ar1 * Kst + kn + as1);
            int kg0 = kn + 2 * k2_0;
            int kg1 = kn + 2 * k2_1;
            const float* B0 = (!mode || kg0 < 256)
                ? x      + ((size_t)b * NC + kg0)         * NL + l0 + cl0
                : d_virt + ((size_t)b * NC + (kg0 - 256)) * NL + l0 + cl0;
            const float* B1 = (!mode || kg1 < 256)
                ? x      + ((size_t)b * NC + kg1)         * NL + l0 + cl1
                : d_virt + ((size_t)b * NC + (kg1 - 256)) * NL + l0 + cl1;
            pb[0] = *(const float4*)B0;
            pb[1] = *(const float4*)(B0 + NL);
            pb[2] = *(const float4*)B1;
            pb[3] = *(const float4*)(B1 + NL);
        }

        // ---- compute: 2 k16-steps x 16 mma ----
#pragma unroll
        for (int ks = 0; ks < 2; ks++) {
            int kb = ks * 16;          // half index base
            int k2b = ks * 8;          // half2 row base
            uint32_t bf[4][2];
#pragma unroll
            for (int nt = 0; nt < 4; nt++) {
                int n = wn + nt * 8 + g;
                bf[nt][0] = *(uint32_t*)&Bs2[st][k2b + tg][n];
                bf[nt][1] = *(uint32_t*)&Bs2[st][k2b + tg + 4][n];
            }
            uint32_t af[4][4];
#pragma unroll
            for (int mt = 0; mt < 4; mt++) {
                int rb = wm + mt * 16;
                af[mt][0] = *(uint32_t*)&As[st][rb + g][kb + 2 * tg];
                af[mt][1] = *(uint32_t*)&As[st][rb + g + 8][kb + 2 * tg];
                af[mt][2] = *(uint32_t*)&As[st][rb + g][kb + 2 * tg + 8];
                af[mt][3] = *(uint32_t*)&As[st][rb + g + 8][kb + 2 * tg + 8];
            }
#pragma unroll
            for (int mt = 0; mt < 4; mt++)
#pragma unroll
                for (int nt = 0; nt < 4; nt++)
                    mma_f16(acc[mt][nt], af[mt], bf[nt]);
        }
    }

    // ---- epilogue: fp32 stores ----
#pragma unroll
    for (int mt = 0; mt < 4; mt++) {
        int m = mbase + wm + mt * 16 + g;
        float* y0 = Ybase + ((size_t)b * NC + m) * NL + l0;
        float* y1 = Ybase + ((size_t)b * NC + m + 8) * NL + l0;
#pragma unroll
        for (int nt = 0; nt < 4; nt++) {
            int l = wn + nt * 8 + 2 * tg;
            y0[l]     = acc[mt][nt][0];
            y0[l + 1] = acc[mt][nt][1];
            y1[l]     = acc[mt][nt][2];
            y1[l + 1] = acc[mt][nt][3];
        }
    }
}

// ---------------- K2: attention per l-tile (LT=4) --------------------------
#define SP_STR 260
#define SX_STR 36
#define SV_STR 132
#define K2_SMEM ((64 * SP_STR + 64 * SV_STR) * 4)

__global__ __launch_bounds__(256, 2) void k2_attn(const float* __restrict__ x) {
    extern __shared__ float smemf[];
    float* sP = smemf;
    float* sX = smemf + 64 * SP_STR;
    float* sG = sX + 64 * SX_STR;
    float* sV = smemf + 64 * SP_STR;

    int tid = threadIdx.x;
    int lt  = blockIdx.x * LT;
    int tb  = tid & 15;
    int td  = tid >> 4;

    float acc[4][4][4];
#pragma unroll
    for (int i = 0; i < 4; i++)
#pragma unroll
        for (int j = 0; j < 4; j++)
#pragma unroll
            for (int l = 0; l < 4; l++) acc[i][j][l] = 0.f;

    for (int c0 = 0; c0 < NC; c0 += 8) {
#pragma unroll
        for (int j = 0; j < 2; j++) {
            int t  = tid + j * 256;
            int bb = t >> 3, cc = t & 7;
            *(float4*)&sX[bb * SX_STR + cc * 4] =
                *(const float4*)(x   + ((size_t)bb * NC + c0 + cc) * NL + lt);
            *(float4*)&sG[bb * SX_STR + cc * 4] =
                *(const float4*)(d_g + ((size_t)bb * NC + c0 + cc) * NL + lt);
        }
        __syncthreads();
#pragma unroll
        for (int cc = 0; cc < 8; cc++) {
            float4 xv[4], gv[4];
#pragma unroll
            for (int i = 0; i < 4; i++)
                xv[i] = *(float4*)&sX[(tb + 16 * i) * SX_STR + cc * 4];
#pragma unroll
            for (int i = 0; i < 4; i++)
                gv[i] = *(float4*)&sG[(td + 16 * i) * SX_STR + cc * 4];
#pragma unroll
            for (int bi = 0; bi < 4; bi++)
#pragma unroll
                for (int di = 0; di < 4; di++) {
                    acc[bi][di][0] += xv[bi].x * gv[di].x;
                    acc[bi][di][1] += xv[bi].y * gv[di].y;
                    acc[bi][di][2] += xv[bi].z * gv[di].z;
                    acc[bi][di][3] += xv[bi].w * gv[di].w;
                }
        }
        __syncthreads();
    }
#pragma unroll
    for (int bi = 0; bi < 4; bi++)
#pragma unroll
        for (int di = 0; di < 4; di++)
#pragma unroll
            for (int l = 0; l < 4; l++)
                sP[(tb + 16 * bi) * SP_STR + (td + 16 * di) * 4 + l] = acc[bi][di][l];
    __syncthreads();

    {
        int b = tid >> 2, l = tid & 3;
        float* row = sP + b * SP_STR + l;
        float mx = -1e30f;
#pragma unroll 8
        for (int d = 0; d < 64; d++) mx = fmaxf(mx, row[d * 4]);
        float s = 0.f;
#pragma unroll 8
        for (int d = 0; d < 64; d++) {
            float e = __expf(row[d * 4] - mx);
            row[d * 4] = e;
            s += e;
        }
        float inv = 1.f / s;
#pragma unroll 8
        for (int d = 0; d < 64; d++) row[d * 4] *= inv;
    }
    __syncthreads();

    int tc = tid >> 4;
    for (int c0 = 0; c0 < NC; c0 += 32) {
#pragma unroll
        for (int j = 0; j < 8; j++) {
            int t  = tid + j * 256;
            int dd = t >> 5, ci = t & 31;
            *(float4*)&sV[dd * SV_STR + ci * 4] =
                *(const float4*)(d_v + ((size_t)dd * NC + c0 + ci) * NL + lt);
        }
        __syncthreads();
        float a3[4][2][4];
#pragma unroll
        for (int i = 0; i < 4; i++)
#pragma unroll
            for (int j = 0; j < 2; j++)
#pragma unroll
                for (int l = 0; l < 4; l++) a3[i][j][l] = 0.f;
#pragma unroll 4
        for (int d = 0; d < 64; d++) {
            float4 p[4];
#pragma unroll
            for (int i = 0; i < 4; i++)
                p[i] = *(float4*)&sP[(tb + 16 * i) * SP_STR + d * 4];
            float4 vv[2];
#pragma unroll
            for (int i = 0; i < 2; i++)
                vv[i] = *(float4*)&sV[d * SV_STR + (tc + 16 * i) * 4];
#pragma unroll
            for (int bi = 0; bi < 4; bi++)
#pragma unroll
                for (int ci = 0; ci < 2; ci++) {
                    a3[bi][ci][0] += p[bi].x * vv[ci].x;
                    a3[bi][ci][1] += p[bi].y * vv[ci].y;
                    a3[bi][ci][2] += p[bi].z * vv[ci].z;
                    a3[bi][ci][3] += p[bi].w * vv[ci].w;
                }
        }
#pragma unroll
        for (int bi = 0; bi < 4; bi++)
#pragma unroll
            for (int ci = 0; ci < 2; ci++) {
                float4 o4 = make_float4(a3[bi][ci][0], a3[bi][ci][1],
                                        a3[bi][ci][2], a3[bi][ci][3]);
                *(float4*)(d_virt + ((size_t)(tb + 16 * bi) * NC + c0 + tc + 16 * ci) * NL + lt) = o4;
            }
        __syncthreads();
    }
}

// ---------------- K3: per-batch GroupNorm stats (deterministic) ------------
__global__ void k3_stats() {
    int b   = blockIdx.x;
    int tid = threadIdx.x;
    const float4* p = (const float4*)(d_virt + (size_t)b * NC * NL);
    float s = 0.f, q = 0.f;
    for (int j = 0; j < 1024; j++) {
        float4 v = p[tid + j * 256];
        s += v.x + v.y + v.z + v.w;
        q += v.x * v.x + v.y * v.y + v.z * v.z + v.w * v.w;
    }
    __shared__ float ss[256], sq[256];
    ss[tid] = s; sq[tid] = q;
    __syncthreads();
    for (int st = 128; st > 0; st >>= 1) {
        if (tid < st) { ss[tid] += ss[tid + st]; sq[tid] += sq[tid + st]; }
        __syncthreads();
    }
    if (tid == 0) {
        float N    = (float)(NC * NL);
        float mean = ss[0] / N;
        float var  = sq[0] / N - mean * mean;
        d_mean[b] = mean;
        d_rstd[b] = rsqrtf(var + 1e-5f);
    }
}

// ---------------- launch ----------------------------------------------------
extern "C" void kernel_launch(void* const* d_in, const int* in_sizes, int n_in,
                              void* d_out, int out_size) {
    const float* x     = (const float*)d_in[0];
    const float* Wq    = (const float*)d_in[1];
    const float* Wk    = (const float*)d_in[2];
    const float* Wv    = (const float*)d_in[3];
    const float* Wc    = (const float*)d_in[4];
    const float* Wout  = (const float*)d_in[5];
    const float* gamma = (const float*)d_in[6];
    const float* beta  = (const float*)d_in[7];
    float* out = (float*)d_out;

    cudaFuncSetAttribute(k2_attn, cudaFuncAttributeMaxDynamicSharedMemorySize, K2_SMEM);

    dim3 b16(16, 16);
    k0_M <<<dim3(16, 16), b16>>>(Wq, Wk);
    k0_W2<<<dim3(16, 16), b16>>>(Wout, Wc);
    kprep_Ah<<<512, 256>>>(Wv, Wout);

    k_gemm<<<dim3(4, NL / 128, NB), 256>>>(0, nullptr, x, gamma, beta);

    k2_attn<<<NL / LT, 256, K2_SMEM>>>(x);
    k3_stats<<<NB, 256>>>();

    k_gemm<<<dim3(2, NL / 128, NB), 256>>>(1, out, x, gamma, beta);
}

// round 15
// speedup vs baseline: 1.9334x; 1.1494x over previous
#include <cuda_runtime.h>
#include <cuda_fp16.h>
#include <cstdint>
#include <cstddef>

#define NB 64
#define NC 256
#define NL 4096
#define LT 4

// ---------------- scratch (device globals; no allocation allowed) ----------
__device__ float d_M [NC * NC];                 // Wq^T Wk / sqrt(C)
__device__ float d_W2[NC * NC];                 // Wout @ Wc
__device__ float d_g   [(size_t)NB * NC * NL];  // M @ x
__device__ float d_v   [(size_t)NB * NC * NL];  // Wv @ x
__device__ __half d_virt_h[(size_t)NB * NC * NL];  // attention output (fp16)
__device__ float d_mean[NB];
__device__ float d_rstd[NB];
__device__ float d_pS[(NL / LT) * NB];          // per-CTA partial sums
__device__ float d_pQ[(NL / LT) * NB];
__device__ __half d_A0h[512 * 256];             // fp16([M ; Wv])
__device__ __half d_A1h[256 * 512];             // fp16([Wout | W2])

// ---------------- helpers ---------------------------------------------------
__device__ __forceinline__ void mma_f16(float* c, const uint32_t* a,
                                        const uint32_t* b) {
    asm volatile(
        "mma.sync.aligned.m16n8k16.row.col.f32.f16.f16.f32 "
        "{%0,%1,%2,%3}, {%4,%5,%6,%7}, {%8,%9}, {%0,%1,%2,%3};"
        : "+f"(c[0]), "+f"(c[1]), "+f"(c[2]), "+f"(c[3])
        : "r"(a[0]), "r"(a[1]), "r"(a[2]), "r"(a[3]), "r"(b[0]), "r"(b[1]));
}

// ---------------- K0: M = Wq^T Wk / 16 -------------------------------------
__global__ void k0_M(const float* __restrict__ Wq, const float* __restrict__ Wk) {
    __shared__ float sA[16][17], sB[16][17];
    int tx = threadIdx.x, ty = threadIdx.y;
    int c1 = blockIdx.y * 16 + ty;
    int c2 = blockIdx.x * 16 + tx;
    float acc = 0.f;
    for (int o0 = 0; o0 < NC; o0 += 16) {
        sA[ty][tx] = Wq[(o0 + ty) * NC + blockIdx.y * 16 + tx];
        sB[ty][tx] = Wk[(o0 + ty) * NC + blockIdx.x * 16 + tx];
        __syncthreads();
#pragma unroll
        for (int i = 0; i < 16; i++) acc += sA[i][ty] * sB[i][tx];
        __syncthreads();
    }
    d_M[c1 * NC + c2] = acc * 0.0625f;
}

// ---------------- K0b: W2 = Wout @ Wc --------------------------------------
__global__ void k0_W2(const float* __restrict__ Wout, const float* __restrict__ Wc) {
    __shared__ float sA[16][17], sB[16][17];
    int tx = threadIdx.x, ty = threadIdx.y;
    int o = blockIdx.y * 16 + ty;
    int c = blockIdx.x * 16 + tx;
    float acc = 0.f;
    for (int m0 = 0; m0 < NC; m0 += 16) {
        sA[ty][tx] = Wout[o * NC + m0 + tx];
        sB[ty][tx] = Wc[(m0 + ty) * NC + blockIdx.x * 16 + tx];
        __syncthreads();
#pragma unroll
        for (int i = 0; i < 16; i++) acc += sA[ty][i] * sB[i][tx];
        __syncthreads();
    }
    d_W2[o * NC + c] = acc;
}

// ---------------- prepass: A matrices -> fp16 --------------------------------
__global__ void kprep_Ah(const float* __restrict__ Wv, const float* __restrict__ Wout) {
    int i = blockIdx.x * 256 + threadIdx.x;          // 0..131071
    d_A0h[i] = __float2half((i < 65536) ? d_M[i] : Wv[i - 65536]);
    int r = i >> 9, k = i & 511;
    d_A1h[i] = __float2half((k < 256) ? Wout[r * 256 + k] : d_W2[r * 256 + (k - 256)]);
}

// ---------------- FP16 tensor-core GEMM (A+B reg prefetch, dbl-buffer) ------
// mode 0: Y[512,L] = [M ; Wv] @ x[b]          -> d_g / d_v   (K = 256)
// mode 1: out[256,L] = [Wout|W2] @ [x ; relu(gn(virt_h))]    (K = 512)
__global__ __launch_bounds__(256, 2) void k_gemm(int mode, float* __restrict__ out,
                                                 const float* __restrict__ x,
                                                 const float* __restrict__ gamma,
                                                 const float* __restrict__ beta) {
    __shared__ __half  As[2][128][40];   // bank=(20g+tg)%32 bijective
    __shared__ __half2 Bs2[2][16][136];  // half2=(k even,k odd); bank=(8tg+g)%32

    int tid = threadIdx.x;
    int b   = blockIdx.z;
    int l0  = blockIdx.y * 128;
    int m0  = blockIdx.x * 128;
    int nch = mode ? 16 : 8;
    int Kst = mode ? 512 : 256;
    const __half* Ah = (mode ? d_A1h : d_A0h) + (size_t)m0 * Kst;

    float* Ybase;
    int mbase;
    if (mode == 0) {
        if (m0 < 256) { Ybase = d_g; mbase = m0; }
        else          { Ybase = d_v; mbase = m0 - 256; }
    } else {
        Ybase = out; mbase = m0;
    }

    float mn = 0.f, rs = 0.f;
    if (mode) { mn = d_mean[b]; rs = d_rstd[b]; }

    int lane = tid & 31, w = tid >> 5;
    int g = lane >> 2, tg = lane & 3;
    int wm = (w & 1) * 64, wn = (w >> 1) * 32;

    float acc[4][4][4];
#pragma unroll
    for (int mt = 0; mt < 4; mt++)
#pragma unroll
        for (int nt = 0; nt < 4; nt++)
#pragma unroll
            for (int i = 0; i < 4; i++) acc[mt][nt][i] = 0.f;

    // per-thread staging coordinates (fixed across chunks)
    int ar0 = tid >> 2,          as0 = (tid & 3) * 8;
    int ar1 = (tid + 256) >> 2,  as1 = (tid & 3) * 8;
    int k2_0 = tid >> 5,         cl0 = (tid & 31) * 4;
    int k2_1 = (tid + 256) >> 5, cl1 = (tid & 31) * 4;

    // ---- prefetch chunk 0 ----
    uint4  pa[2];
    float4 pb[4];
    uint2  pv[4];
    pa[0] = *(const uint4*)(Ah + (size_t)ar0 * Kst + as0);
    pa[1] = *(const uint4*)(Ah + (size_t)ar1 * Kst + as1);
    {
        const float* B0 = x + ((size_t)b * NC + 2 * k2_0) * NL + l0 + cl0;
        const float* B1 = x + ((size_t)b * NC + 2 * k2_1) * NL + l0 + cl1;
        pb[0] = *(const float4*)B0;
        pb[1] = *(const float4*)(B0 + NL);
        pb[2] = *(const float4*)B1;
        pb[3] = *(const float4*)(B1 + NL);
    }

#pragma unroll 1
    for (int ch = 0; ch < nch; ch++) {
        int st = ch & 1;
        int k0 = ch * 32;
        bool vch = mode && (k0 >= 256);
        // ---- stage A from regs ----
        *(uint4*)&As[st][ar0][as0] = pa[0];
        *(uint4*)&As[st][ar1][as1] = pa[1];
        // ---- stage B from regs (cvt + optional gn/relu) ----
#pragma unroll
        for (int j = 0; j < 2; j++) {
            int k2 = j ? k2_1 : k2_0;
            int cl = j ? cl1 : cl0;
            int kg = k0 + 2 * k2;
            float4 v0, v1;
            if (!vch) {
                v0 = pb[2 * j]; v1 = pb[2 * j + 1];
            } else {
                __half2* h0 = (__half2*)&pv[2 * j];
                __half2* h1 = (__half2*)&pv[2 * j + 1];
                float2 a01 = __half22float2(h0[0]), a23 = __half22float2(h0[1]);
                float2 b01 = __half22float2(h1[0]), b23 = __half22float2(h1[1]);
                v0 = make_float4(a01.x, a01.y, a23.x, a23.y);
                v1 = make_float4(b01.x, b01.y, b23.x, b23.y);
                int c0 = kg - 256, c1 = c0 + 1;
                float g0 = gamma[c0] * rs, bb0 = beta[c0] - mn * g0;
                float g1 = gamma[c1] * rs, bb1 = beta[c1] - mn * g1;
                v0.x = fmaxf(fmaf(v0.x, g0, bb0), 0.f);
                v0.y = fmaxf(fmaf(v0.y, g0, bb0), 0.f);
                v0.z = fmaxf(fmaf(v0.z, g0, bb0), 0.f);
                v0.w = fmaxf(fmaf(v0.w, g0, bb0), 0.f);
                v1.x = fmaxf(fmaf(v1.x, g1, bb1), 0.f);
                v1.y = fmaxf(fmaf(v1.y, g1, bb1), 0.f);
                v1.z = fmaxf(fmaf(v1.z, g1, bb1), 0.f);
                v1.w = fmaxf(fmaf(v1.w, g1, bb1), 0.f);
            }
            Bs2[st][k2][cl]     = __floats2half2_rn(v0.x, v1.x);
            Bs2[st][k2][cl + 1] = __floats2half2_rn(v0.y, v1.y);
            Bs2[st][k2][cl + 2] = __floats2half2_rn(v0.z, v1.z);
            Bs2[st][k2][cl + 3] = __floats2half2_rn(v0.w, v1.w);
        }
        __syncthreads();

        // ---- issue prefetch for next chunk ----
        if (ch + 1 < nch) {
            int kn = (ch + 1) * 32;
            pa[0] = *(const uint4*)(Ah + (size_t)ar0 * Kst + kn + as0);
            pa[1] = *(const uint4*)(Ah + (size_t)ar1 * Kst + kn + as1);
            int kg0 = kn + 2 * k2_0;
            int kg1 = kn + 2 * k2_1;
            if (!(mode && kn >= 256)) {
                const float* B0 = x + ((size_t)b * NC + kg0) * NL + l0 + cl0;
                const float* B1 = x + ((size_t)b * NC + kg1) * NL + l0 + cl1;
                pb[0] = *(const float4*)B0;
                pb[1] = *(const float4*)(B0 + NL);
                pb[2] = *(const float4*)B1;
                pb[3] = *(const float4*)(B1 + NL);
            } else {
                const __half* H0 = d_virt_h + ((size_t)b * NC + (kg0 - 256)) * NL + l0 + cl0;
                const __half* H1 = d_virt_h + ((size_t)b * NC + (kg1 - 256)) * NL + l0 + cl1;
                pv[0] = *(const uint2*)H0;
                pv[1] = *(const uint2*)(H0 + NL);
                pv[2] = *(const uint2*)H1;
                pv[3] = *(const uint2*)(H1 + NL);
            }
        }

        // ---- compute: 2 k16-steps x 16 mma ----
#pragma unroll
        for (int ks = 0; ks < 2; ks++) {
            int kb = ks * 16;
            int k2b = ks * 8;
            uint32_t bf[4][2];
#pragma unroll
            for (int nt = 0; nt < 4; nt++) {
                int n = wn + nt * 8 + g;
                bf[nt][0] = *(uint32_t*)&Bs2[st][k2b + tg][n];
                bf[nt][1] = *(uint32_t*)&Bs2[st][k2b + tg + 4][n];
            }
            uint32_t af[4][4];
#pragma unroll
            for (int mt = 0; mt < 4; mt++) {
                int rb = wm + mt * 16;
                af[mt][0] = *(uint32_t*)&As[st][rb + g][kb + 2 * tg];
                af[mt][1] = *(uint32_t*)&As[st][rb + g + 8][kb + 2 * tg];
                af[mt][2] = *(uint32_t*)&As[st][rb + g][kb + 2 * tg + 8];
                af[mt][3] = *(uint32_t*)&As[st][rb + g + 8][kb + 2 * tg + 8];
            }
#pragma unroll
            for (int mt = 0; mt < 4; mt++)
#pragma unroll
                for (int nt = 0; nt < 4; nt++)
                    mma_f16(acc[mt][nt], af[mt], bf[nt]);
        }
    }

    // ---- epilogue: fp32 stores ----
#pragma unroll
    for (int mt = 0; mt < 4; mt++) {
        int m = mbase + wm + mt * 16 + g;
        float* y0 = Ybase + ((size_t)b * NC + m) * NL + l0;
        float* y1 = Ybase + ((size_t)b * NC + m + 8) * NL + l0;
#pragma unroll
        for (int nt = 0; nt < 4; nt++) {
            int l = wn + nt * 8 + 2 * tg;
            y0[l]     = acc[mt][nt][0];
            y0[l + 1] = acc[mt][nt][1];
            y1[l]     = acc[mt][nt][2];
            y1[l + 1] = acc[mt][nt][3];
        }
    }
}

// ---------------- K2: attention per l-tile (LT=4), fused stats --------------
// smem: region0 (16640 f): sP (phases 1-2) -> sV (phase 3)
//       region1 (8320 f):  sX+sG (phase 1) -> sPh fp16 (phases 2-3) -> sRS/sRQ
#define SP_STR  260
#define SX_STR  36
#define SV2_STR 260
#define PH_STR  260
#define K2_SMEM ((16640 + 8320) * 4)

__global__ __launch_bounds__(256, 2) void k2_attn(const float* __restrict__ x) {
    extern __shared__ float smemf[];
    float*  sP  = smemf;                       // [64][260] fp32 att
    float*  sX  = smemf + 16640;               // [64][36]
    float*  sG  = sX + 64 * SX_STR;            // [64][36]
    __half* sPh = (__half*)(smemf + 16640);    // [64][260] fp16 P (after phase 1)
    float*  sV  = smemf;                       // [64][260] V tile (phase 3)
    float*  sRS = smemf + 16640;               // [8][64] partial sums (after ph3)
    float*  sRQ = sRS + 512;

    int tid = threadIdx.x;
    int lt  = blockIdx.x * LT;
    int tb  = tid & 15;
    int td  = tid >> 4;

    // ---- phase 1: att[b,d,l] = sum_c x[b,c,l] * g[d,c,l] ----
    {
        float acc[4][4][4];
#pragma unroll
        for (int i = 0; i < 4; i++)
#pragma unroll
            for (int j = 0; j < 4; j++)
#pragma unroll
                for (int l = 0; l < 4; l++) acc[i][j][l] = 0.f;

        for (int c0 = 0; c0 < NC; c0 += 8) {
#pragma unroll
            for (int j = 0; j < 2; j++) {
                int t  = tid + j * 256;
                int bb = t >> 3, cc = t & 7;
                *(float4*)&sX[bb * SX_STR + cc * 4] =
                    *(const float4*)(x   + ((size_t)bb * NC + c0 + cc) * NL + lt);
                *(float4*)&sG[bb * SX_STR + cc * 4] =
                    *(const float4*)(d_g + ((size_t)bb * NC + c0 + cc) * NL + lt);
            }
            __syncthreads();
#pragma unroll
            for (int cc = 0; cc < 8; cc++) {
                float4 xv[4], gv[4];
#pragma unroll
                for (int i = 0; i < 4; i++)
                    xv[i] = *(float4*)&sX[(tb + 16 * i) * SX_STR + cc * 4];
#pragma unroll
                for (int i = 0; i < 4; i++)
                    gv[i] = *(float4*)&sG[(td + 16 * i) * SX_STR + cc * 4];
#pragma unroll
                for (int bi = 0; bi < 4; bi++)
#pragma unroll
                    for (int di = 0; di < 4; di++) {
                        acc[bi][di][0] += xv[bi].x * gv[di].x;
                        acc[bi][di][1] += xv[bi].y * gv[di].y;
                        acc[bi][di][2] += xv[bi].z * gv[di].z;
                        acc[bi][di][3] += xv[bi].w * gv[di].w;
                    }
            }
            __syncthreads();
        }
#pragma unroll
        for (int bi = 0; bi < 4; bi++)
#pragma unroll
            for (int di = 0; di < 4; di++)
#pragma unroll
                for (int l = 0; l < 4; l++)
                    sP[(tb + 16 * bi) * SP_STR + (td + 16 * di) * 4 + l] = acc[bi][di][l];
        __syncthreads();
    }

    // ---- phase 2: softmax over d; write P as fp16 into sPh ----
    {
        int b = tid >> 2, l = tid & 3;
        float* row = sP + b * SP_STR + l;
        float mx = -1e30f;
#pragma unroll 8
        for (int d = 0; d < 64; d++) mx = fmaxf(mx, row[d * 4]);
        float s = 0.f;
        float e_[64];
#pragma unroll 8
        for (int d = 0; d < 64; d++) {
            float e = __expf(row[d * 4] - mx);
            e_[d] = e;
            s += e;
        }
        float inv = 1.f / s;
        __syncthreads();   // all reads of sP done before sPh (region1) writes race? sPh != sP region; barrier guards sX/sG reuse
#pragma unroll 8
        for (int d = 0; d < 64; d++)
            sPh[b * PH_STR + d * 4 + l] = __float2half(e_[d] * inv);
    }
    __syncthreads();

    // ---- phase 3: virt[b,c,l] = sum_d P[b,d,l] * v[d,c,l] (c-chunk 64) ----
    int tc = tid >> 4;
    float s4[4] = {0.f, 0.f, 0.f, 0.f};
    float q4[4] = {0.f, 0.f, 0.f, 0.f};
    for (int c0 = 0; c0 < NC; c0 += 64) {
#pragma unroll
        for (int j = 0; j < 16; j++) {
            int t  = tid + j * 256;
            int dd = t >> 6, cq = t & 63;
            *(float4*)&sV[dd * SV2_STR + cq * 4] =
                *(const float4*)(d_v + ((size_t)dd * NC + c0 + cq) * NL + lt);
        }
        __syncthreads();
        float a3[4][4][4];
#pragma unroll
        for (int i = 0; i < 4; i++)
#pragma unroll
            for (int j = 0; j < 4; j++)
#pragma unroll
                for (int l = 0; l < 4; l++) a3[i][j][l] = 0.f;
#pragma unroll 2
        for (int d = 0; d < 64; d++) {
            float4 p[4];
#pragma unroll
            for (int bi = 0; bi < 4; bi++) {
                uint2 ph = *(uint2*)&sPh[(tb + 16 * bi) * PH_STR + d * 4];
                float2 p01 = __half22float2(*(__half2*)&ph.x);
                float2 p23 = __half22float2(*(__half2*)&ph.y);
                p[bi] = make_float4(p01.x, p01.y, p23.x, p23.y);
            }
            float4 vv[4];
#pragma unroll
            for (int ci = 0; ci < 4; ci++)
                vv[ci] = *(float4*)&sV[d * SV2_STR + (tc + 16 * ci) * 4];
#pragma unroll
            for (int bi = 0; bi < 4; bi++)
#pragma unroll
                for (int ci = 0; ci < 4; ci++) {
                    a3[bi][ci][0] += p[bi].x * vv[ci].x;
                    a3[bi][ci][1] += p[bi].y * vv[ci].y;
                    a3[bi][ci][2] += p[bi].z * vv[ci].z;
                    a3[bi][ci][3] += p[bi].w * vv[ci].w;
                }
        }
        // stores (fp16) + stats accumulation (fp32, pre-rounding)
#pragma unroll
        for (int bi = 0; bi < 4; bi++)
#pragma unroll
            for (int ci = 0; ci < 4; ci++) {
                float v0 = a3[bi][ci][0], v1 = a3[bi][ci][1];
                float v2 = a3[bi][ci][2], v3 = a3[bi][ci][3];
                s4[bi] += (v0 + v1) + (v2 + v3);
                q4[bi] += (v0 * v0 + v1 * v1) + (v2 * v2 + v3 * v3);
                uint2 u;
                *(__half2*)&u.x = __floats2half2_rn(v0, v1);
                *(__half2*)&u.y = __floats2half2_rn(v2, v3);
                int c = c0 + tc + 16 * ci;
                *(uint2*)(d_virt_h + ((size_t)(tb + 16 * bi) * NC + c) * NL + lt) = u;
            }
        __syncthreads();
    }

    // ---- fused GN stats: deterministic CTA reduction -> global partials ----
#pragma unroll
    for (int bi = 0; bi < 4; bi++) {
        s4[bi] += __shfl_xor_sync(0xffffffffu, s4[bi], 16);
        q4[bi] += __shfl_xor_sync(0xffffffffu, q4[bi], 16);
    }
    int wid = tid >> 5, lane = tid & 31;
    if (lane < 16) {
#pragma unroll
        for (int bi = 0; bi < 4; bi++) {
            sRS[wid * 64 + lane + 16 * bi] = s4[bi];
            sRQ[wid * 64 + lane + 16 * bi] = q4[bi];
        }
    }
    __syncthreads();
    if (tid < 64) {
        float s = 0.f, q = 0.f;
#pragma unroll
        for (int w2 = 0; w2 < 8; w2++) {
            s += sRS[w2 * 64 + tid];
            q += sRQ[w2 * 64 + tid];
        }
        d_pS[blockIdx.x * 64 + tid] = s;
        d_pQ[blockIdx.x * 64 + tid] = q;
    }
}

// ---------------- K3b: finish GN stats from per-CTA partials ----------------
__global__ void k3b() {
    int b = blockIdx.x, tid = threadIdx.x;   // 64 blocks x 256 threads
    float s = 0.f, q = 0.f;
    for (int j = tid; j < NL / LT; j += 256) {
        s += d_pS[j * 64 + b];
        q += d_pQ[j * 64 + b];
    }
    __shared__ float ss[256], sq[256];
    ss[tid] = s; sq[tid] = q;
    __syncthreads();
    for (int st = 128; st > 0; st >>= 1) {
        if (tid < st) { ss[tid] += ss[tid + st]; sq[tid] += sq[tid + st]; }
        __syncthreads();
    }
    if (tid == 0) {
        float N    = (float)(NC * NL);
        float mean = ss[0] / N;
        float var  = sq[0] / N - mean * mean;
        d_mean[b] = mean;
        d_rstd[b] = rsqrtf(var + 1e-5f);
    }
}

// ---------------- launch ----------------------------------------------------
extern "C" void kernel_launch(void* const* d_in, const int* in_sizes, int n_in,
                              void* d_out, int out_size) {
    const float* x     = (const float*)d_in[0];
    const float* Wq    = (const float*)d_in[1];
    const float* Wk    = (const float*)d_in[2];
    const float* Wv    = (const float*)d_in[3];
    const float* Wc    = (const float*)d_in[4];
    const float* Wout  = (const float*)d_in[5];
    const float* gamma = (const float*)d_in[6];
    const float* beta  = (const float*)d_in[7];
    float* out = (float*)d_out;

    cudaFuncSetAttribute(k2_attn, cudaFuncAttributeMaxDynamicSharedMemorySize, K2_SMEM);

    dim3 b16(16, 16);
    k0_M <<<dim3(16, 16), b16>>>(Wq, Wk);
    k0_W2<<<dim3(16, 16), b16>>>(Wout, Wc);
    kprep_Ah<<<512, 256>>>(Wv, Wout);

    k_gemm<<<dim3(4, NL / 128, NB), 256>>>(0, nullptr, x, gamma, beta);

    k2_attn<<<NL / LT, 256, K2_SMEM>>>(x);
    k3b<<<NB, 256>>>();

    k_gemm<<<dim3(2, NL / 128, NB), 256>>>(1, out, x, gamma, beta);
}